// round 3
// baseline (speedup 1.0000x reference)
#include <cuda_runtime.h>
#include <math.h>
#include <stdint.h>

#define B_   64
#define T_   256
#define ID_  512
#define HD_  1024
#define G4_  4096   // 4*HD

#define NB      128          // persistent blocks (each owns 8 hidden units)
#define JPB     8            // hidden units per block (1024/128)
#define KT      64           // K-chunk of h staged in smem per iteration
#define THREADS2 256
#define SMEM2_BYTES (1024*32*4 + KT*64*4)   // Wsm (128KB) + hs (16KB) = 147456

// Scratch: gates_x laid out [t][n][b] so step-t reads are fully coalesced.
__device__ float g_gx[(size_t)T_ * G4_ * B_];   // 256 MB, static (allowed)
__device__ unsigned int g_bar_count = 0;
__device__ unsigned int g_bar_gen   = 0;

// ---------------------------------------------------------------------------
// Phase 1: gx[t][n][b] = sum_k x[b][t][k] * Wi[k][n] + bi[n] + bh[n]
// grid: (4H/64, T/64, B), block 256, 64x64 tile, 4x4 micro-tile
// ---------------------------------------------------------------------------
__global__ void gemm_x_kernel(const float* __restrict__ x,
                              const float* __restrict__ Wi,
                              const float* __restrict__ bi,
                              const float* __restrict__ bh) {
    __shared__ float xs[16][64];   // [k][t]
    __shared__ float ws[16][64];   // [k][n]

    const int b  = blockIdx.z;
    const int t0 = blockIdx.y * 64;
    const int n0 = blockIdx.x * 64;
    const int tid = threadIdx.x;
    const int tm = tid & 15;       // t micro-row group (4 t's)
    const int tn = tid >> 4;       // n micro-col group (4 n's)

    float acc[4][4];
#pragma unroll
    for (int i = 0; i < 4; i++)
#pragma unroll
        for (int jq = 0; jq < 4; jq++) acc[i][jq] = 0.0f;

    const float* xb = x + ((long)b * T_ + t0) * ID_;

    for (int k0 = 0; k0 < ID_; k0 += 16) {
        // load x tile transposed -> xs[k][t]
        {
            int i  = tid >> 2;      // 0..63 (t row)
            int kq = tid & 3;       // 0..3
            float4 v = *(const float4*)(xb + (long)i * ID_ + k0 + 4 * kq);
            xs[4 * kq + 0][i] = v.x;
            xs[4 * kq + 1][i] = v.y;
            xs[4 * kq + 2][i] = v.z;
            xs[4 * kq + 3][i] = v.w;
        }
        // load Wi tile -> ws[k][n]
        {
            int r  = tid >> 4;      // 0..15
            int nq = tid & 15;      // 0..15
            float4 v = *(const float4*)(Wi + (long)(k0 + r) * G4_ + n0 + 4 * nq);
            *(float4*)&ws[r][4 * nq] = v;
        }
        __syncthreads();
#pragma unroll
        for (int k = 0; k < 16; k++) {
            float4 a = *(float4*)&xs[k][4 * tm];
            float4 w = *(float4*)&ws[k][4 * tn];
            acc[0][0] = fmaf(a.x, w.x, acc[0][0]);
            acc[0][1] = fmaf(a.x, w.y, acc[0][1]);
            acc[0][2] = fmaf(a.x, w.z, acc[0][2]);
            acc[0][3] = fmaf(a.x, w.w, acc[0][3]);
            acc[1][0] = fmaf(a.y, w.x, acc[1][0]);
            acc[1][1] = fmaf(a.y, w.y, acc[1][1]);
            acc[1][2] = fmaf(a.y, w.z, acc[1][2]);
            acc[1][3] = fmaf(a.y, w.w, acc[1][3]);
            acc[2][0] = fmaf(a.z, w.x, acc[2][0]);
            acc[2][1] = fmaf(a.z, w.y, acc[2][1]);
            acc[2][2] = fmaf(a.z, w.z, acc[2][2]);
            acc[2][3] = fmaf(a.z, w.w, acc[2][3]);
            acc[3][0] = fmaf(a.w, w.x, acc[3][0]);
            acc[3][1] = fmaf(a.w, w.y, acc[3][1]);
            acc[3][2] = fmaf(a.w, w.z, acc[3][2]);
            acc[3][3] = fmaf(a.w, w.w, acc[3][3]);
        }
        __syncthreads();
    }

#pragma unroll
    for (int i = 0; i < 4; i++) {
        int t = t0 + 4 * tm + i;
#pragma unroll
        for (int jq = 0; jq < 4; jq++) {
            int n = n0 + 4 * tn + jq;
            float bias = __ldg(bi + n) + __ldg(bh + n);
            g_gx[(size_t)t * (G4_ * B_) + (size_t)n * B_ + b] = acc[i][jq] + bias;
        }
    }
}

// ---------------------------------------------------------------------------
// Phase 2: persistent recurrent kernel. Each block owns JPB=8 hidden units
// (all 4 gates) for all 64 batches. Wh slice lives in SMEM across all steps.
// ---------------------------------------------------------------------------
__device__ __forceinline__ float sigf(float v) {
    return 1.0f / (1.0f + expf(-v));
}

__device__ __forceinline__ void grid_barrier() {
    __syncthreads();
    if (threadIdx.x == 0) {
        __threadfence();
        unsigned gen = atomicAdd(&g_bar_gen, 0u);
        unsigned arrived = atomicAdd(&g_bar_count, 1u);
        if (arrived == NB - 1) {
            atomicExch(&g_bar_count, 0u);
            __threadfence();
            atomicAdd(&g_bar_gen, 1u);
        } else {
            while (atomicAdd(&g_bar_gen, 0u) == gen) { __nanosleep(128); }
        }
        __threadfence();
    }
    __syncthreads();
}

extern __shared__ float smem2[];

__global__ void lstm_seq_kernel(const float* __restrict__ Wh,
                                float* __restrict__ out) {
    float* Wsm = smem2;                 // [k][jj][g]: k*32 + jj*4 + g (128 KB)
    float* hs  = smem2 + 1024 * 32;     // [kk][b] (16 KB)

    const int bid  = blockIdx.x;
    const int tid  = threadIdx.x;
    const int bIdx = tid & 31;          // batch group: 2 batches each
    const int jIdx = tid >> 5;          // 0..7
    const int j0   = bid * JPB;
    const int j    = j0 + jIdx;

    float* Q  = out;                               // [B][T][HD]
    float* hT = out + (size_t)B_ * T_ * HD_;
    float* cT = hT + (size_t)B_ * HD_;

    // Load this block's Wh slice into SMEM once (reused 255 times).
    for (int idx = tid; idx < 1024 * 32; idx += THREADS2) {
        int k  = idx >> 5;
        int r  = idx & 31;
        int jj = r >> 2;
        int g  = r & 3;
        Wsm[idx] = Wh[(long)k * G4_ + g * HD_ + j0 + jj];
    }
    __syncthreads();

    float cr0 = 0.0f, cr1 = 0.0f;

    for (int t = 0; t < T_; t++) {
        // init accumulators from gates_x (bias already folded in)
        const float* gxt = g_gx + (size_t)t * (G4_ * B_);
        float2 vf = *(const float2*)(gxt + ((size_t)(0 * HD_ + j)) * B_ + 2 * bIdx);
        float2 vi = *(const float2*)(gxt + ((size_t)(1 * HD_ + j)) * B_ + 2 * bIdx);
        float2 va = *(const float2*)(gxt + ((size_t)(2 * HD_ + j)) * B_ + 2 * bIdx);
        float2 vo = *(const float2*)(gxt + ((size_t)(3 * HD_ + j)) * B_ + 2 * bIdx);
        float af0 = vf.x, af1 = vf.y;
        float ai0 = vi.x, ai1 = vi.y;
        float aa0 = va.x, aa1 = va.y;
        float ao0 = vo.x, ao1 = vo.y;

        if (t > 0) {
            for (int kc = 0; kc < HD_; kc += KT) {
                __syncthreads();
                // stage h(t-1)[b][kc..kc+KT) transposed -> hs[kk][b]
                {
                    int bb = tid & 63;
                    int ms = tid >> 6;   // 0..3
                    const float* hb = Q + ((long)bb * T_ + (t - 1)) * HD_ + kc;
#pragma unroll
                    for (int m = ms; m < KT / 4; m += 4) {
                        float4 v = *(const float4*)(hb + 4 * m);
                        hs[(4 * m + 0) * 64 + bb] = v.x;
                        hs[(4 * m + 1) * 64 + bb] = v.y;
                        hs[(4 * m + 2) * 64 + bb] = v.z;
                        hs[(4 * m + 3) * 64 + bb] = v.w;
                    }
                }
                __syncthreads();
                const float* Wp = Wsm + kc * 32 + jIdx * 4;
#pragma unroll
                for (int kk = 0; kk < KT; kk++) {
                    float2 hv = *(const float2*)(hs + (kk << 6) + 2 * bIdx);
                    float4 wv = *(const float4*)(Wp + (kk << 5));
                    af0 = fmaf(hv.x, wv.x, af0);
                    af1 = fmaf(hv.y, wv.x, af1);
                    ai0 = fmaf(hv.x, wv.y, ai0);
                    ai1 = fmaf(hv.y, wv.y, ai1);
                    aa0 = fmaf(hv.x, wv.z, aa0);
                    aa1 = fmaf(hv.y, wv.z, aa1);
                    ao0 = fmaf(hv.x, wv.w, ao0);
                    ao1 = fmaf(hv.y, wv.w, ao1);
                }
            }
        }

        // elementwise gates for 2 batches
        {
            float f = sigf(af0), ig = sigf(ai0), a = tanhf(aa0), o = sigf(ao0);
            cr0 = f * cr0 + ig * a;
            float hv = o * tanhf(cr0);
            int b = 2 * bIdx + 0;
            Q[((long)b * T_ + t) * HD_ + j] = hv;
            if (t == T_ - 1) { hT[(long)b * HD_ + j] = hv; cT[(long)b * HD_ + j] = cr0; }
        }
        {
            float f = sigf(af1), ig = sigf(ai1), a = tanhf(aa1), o = sigf(ao1);
            cr1 = f * cr1 + ig * a;
            float hv = o * tanhf(cr1);
            int b = 2 * bIdx + 1;
            Q[((long)b * T_ + t) * HD_ + j] = hv;
            if (t == T_ - 1) { hT[(long)b * HD_ + j] = hv; cT[(long)b * HD_ + j] = cr1; }
        }

        if (t < T_ - 1) grid_barrier();
    }
}

// ---------------------------------------------------------------------------
extern "C" void kernel_launch(void* const* d_in, const int* in_sizes, int n_in,
                              void* d_out, int out_size) {
    (void)in_sizes; (void)n_in; (void)out_size;
    const float* x  = (const float*)d_in[0];
    const float* Wi = (const float*)d_in[1];
    const float* bi = (const float*)d_in[2];
    const float* Wh = (const float*)d_in[3];
    const float* bh = (const float*)d_in[4];
    float* out = (float*)d_out;

    cudaFuncSetAttribute(lstm_seq_kernel,
                         cudaFuncAttributeMaxDynamicSharedMemorySize, SMEM2_BYTES);

    dim3 g1(G4_ / 64, T_ / 64, B_);
    gemm_x_kernel<<<g1, 256>>>(x, Wi, bi, bh);
    lstm_seq_kernel<<<NB, THREADS2, SMEM2_BYTES>>>(Wh, out);
}

// round 7
// speedup vs baseline: 4.3642x; 4.3642x over previous
#include <cuda_runtime.h>
#include <cuda_fp16.h>
#include <math.h>
#include <stdint.h>

#define B_   64
#define T_   256
#define ID_  512
#define HD_  1024
#define G4_  4096

#define NBLK     128
#define THREADS2 256

// SMEM layout (dynamic)
#define OFF_W    0                      // 4096 uint4 = 64 KB (A fragments)
#define OFF_HB   65536                  // 2 x 2048 uint4 = 64 KB (B fragment chunks)
#define OFF_DSM  131072                 // 32 x 66 floats = 8448 B
#define SMEM2    (OFF_DSM + 32*66*4)    // 139520

__device__ float g_gx[(size_t)T_ * G4_ * B_];        // [t][m_packed][b]
__device__ uint4 g_wpack[(size_t)NBLK * 4096];       // per-block A-fragment images (8 MB)
__device__ uint4 g_hfrag[2][8192];                   // B-fragment images, 128 KB each
__device__ unsigned int g_bar_count = 0;
__device__ unsigned int g_bar_gen   = 0;

// ---------------- helpers ----------------------------------------------------
__device__ __forceinline__ uint32_t smem_u32(const void* p) {
    uint32_t a;
    asm("{ .reg .u64 t; cvta.to.shared.u64 t, %1; cvt.u32.u64 %0, t; }" : "=r"(a) : "l"(p));
    return a;
}
__device__ __forceinline__ void cp_async16(uint32_t dst, const void* src) {
    asm volatile("cp.async.cg.shared.global [%0], [%1], 16;" :: "r"(dst), "l"(src) : "memory");
}
__device__ __forceinline__ void cp_commit() {
    asm volatile("cp.async.commit_group;" ::: "memory");
}
__device__ __forceinline__ void cp_wait1() {
    asm volatile("cp.async.wait_group 1;" ::: "memory");
}
__device__ __forceinline__ void cp_wait0() {
    asm volatile("cp.async.wait_group 0;" ::: "memory");
}
__device__ __forceinline__ void mma16816(float& d0, float& d1, float& d2, float& d3,
                                         uint32_t a0, uint32_t a1, uint32_t a2, uint32_t a3,
                                         uint32_t b0, uint32_t b1) {
    asm volatile(
        "mma.sync.aligned.m16n8k16.row.col.f32.f16.f16.f32 "
        "{%0,%1,%2,%3}, {%4,%5,%6,%7}, {%8,%9}, {%0,%1,%2,%3};"
        : "+f"(d0), "+f"(d1), "+f"(d2), "+f"(d3)
        : "r"(a0), "r"(a1), "r"(a2), "r"(a3), "r"(b0), "r"(b1));
}
__device__ __forceinline__ uint32_t f2h2(float lo, float hi) {
    __half2 h = __floats2half2_rn(lo, hi);
    return *(uint32_t*)&h;
}
__device__ __forceinline__ float sigf(float x) {
    return __fdividef(1.0f, 1.0f + __expf(-x));
}
__device__ __forceinline__ float tanhfa(float x) {
    return fmaf(2.0f, sigf(2.0f * x), -1.0f);
}
__device__ __forceinline__ void grid_barrier() {
    __syncthreads();
    if (threadIdx.x == 0) {
        __threadfence();
        unsigned gen = atomicAdd(&g_bar_gen, 0u);
        unsigned arrived = atomicAdd(&g_bar_count, 1u);
        if (arrived == NBLK - 1) {
            atomicExch(&g_bar_count, 0u);
            __threadfence();
            atomicAdd(&g_bar_gen, 1u);
        } else {
            while (atomicAdd(&g_bar_gen, 0u) == gen) { __nanosleep(64); }
        }
        __threadfence();
    }
    __syncthreads();
}

// ---------------------------------------------------------------------------
// Phase 0: pack Wh into per-block A-fragment images (fp16).
// Block rows m=0..31: m = jl*4+g, j = bid*8+jl.  A[m][k] = Wh[k][g*1024+j].
// Fragment (m16n8k16 A): lane(gid,tig) holds
//   u0=A[gid][2tig..+1], u1=A[gid+8][..], u2=A[gid][2tig+8..+9], u3=A[gid+8][..]
// stored at g_wpack[bid*4096 + ((mt*64+ks)*32 + lane)]
// ---------------------------------------------------------------------------
__global__ void pack_w_kernel(const float* __restrict__ Wh) {
    int bid = blockIdx.x, ks = blockIdx.y;
    int tid = threadIdx.x;          // 64 threads
    int mt = tid >> 5, lane = tid & 31;
    int gid = lane >> 2, tig = lane & 3;

    int r0 = mt * 16 + gid;         // row in [0,32)
    int r1 = r0 + 8;
    int c0 = ((r0 & 3) << 10) + bid * 8 + (r0 >> 2);
    int c1 = ((r1 & 3) << 10) + bid * 8 + (r1 >> 2);
    int k0 = ks * 16 + tig * 2;

    const float* W0 = Wh + c0;
    const float* W1 = Wh + c1;
    uint4 v;
    v.x = f2h2(W0[(size_t)k0 * G4_],       W0[(size_t)(k0 + 1) * G4_]);
    v.y = f2h2(W1[(size_t)k0 * G4_],       W1[(size_t)(k0 + 1) * G4_]);
    v.z = f2h2(W0[(size_t)(k0 + 8) * G4_], W0[(size_t)(k0 + 9) * G4_]);
    v.w = f2h2(W1[(size_t)(k0 + 8) * G4_], W1[(size_t)(k0 + 9) * G4_]);
    g_wpack[(size_t)bid * 4096 + ((mt * 64 + ks) * 32 + lane)] = v;
}

// ---------------------------------------------------------------------------
// Phase 1: gx[t][m][b] = x@Wi + bi + bh,  m = (j>>3)*32 + (j&7)*4 + g
// ---------------------------------------------------------------------------
__global__ void gemm_x_kernel(const float* __restrict__ x,
                              const float* __restrict__ Wi,
                              const float* __restrict__ bi,
                              const float* __restrict__ bh) {
    __shared__ float xs[16][64];
    __shared__ float ws[16][64];

    const int b  = blockIdx.z;
    const int t0 = blockIdx.y * 64;
    const int n0 = blockIdx.x * 64;
    const int tid = threadIdx.x;
    const int tm = tid & 15;
    const int tn = tid >> 4;

    float acc[4][4];
#pragma unroll
    for (int i = 0; i < 4; i++)
#pragma unroll
        for (int jq = 0; jq < 4; jq++) acc[i][jq] = 0.0f;

    const float* xb = x + ((long)b * T_ + t0) * ID_;

    for (int k0 = 0; k0 < ID_; k0 += 16) {
        {
            int i = tid >> 2, kq = tid & 3;
            float4 v = *(const float4*)(xb + (long)i * ID_ + k0 + 4 * kq);
            xs[4 * kq + 0][i] = v.x; xs[4 * kq + 1][i] = v.y;
            xs[4 * kq + 2][i] = v.z; xs[4 * kq + 3][i] = v.w;
        }
        {
            int r = tid >> 4, nq = tid & 15;
            *(float4*)&ws[r][4 * nq] = *(const float4*)(Wi + (long)(k0 + r) * G4_ + n0 + 4 * nq);
        }
        __syncthreads();
#pragma unroll
        for (int k = 0; k < 16; k++) {
            float4 a = *(float4*)&xs[k][4 * tm];
            float4 w = *(float4*)&ws[k][4 * tn];
            acc[0][0] = fmaf(a.x, w.x, acc[0][0]); acc[0][1] = fmaf(a.x, w.y, acc[0][1]);
            acc[0][2] = fmaf(a.x, w.z, acc[0][2]); acc[0][3] = fmaf(a.x, w.w, acc[0][3]);
            acc[1][0] = fmaf(a.y, w.x, acc[1][0]); acc[1][1] = fmaf(a.y, w.y, acc[1][1]);
            acc[1][2] = fmaf(a.y, w.z, acc[1][2]); acc[1][3] = fmaf(a.y, w.w, acc[1][3]);
            acc[2][0] = fmaf(a.z, w.x, acc[2][0]); acc[2][1] = fmaf(a.z, w.y, acc[2][1]);
            acc[2][2] = fmaf(a.z, w.z, acc[2][2]); acc[2][3] = fmaf(a.z, w.w, acc[2][3]);
            acc[3][0] = fmaf(a.w, w.x, acc[3][0]); acc[3][1] = fmaf(a.w, w.y, acc[3][1]);
            acc[3][2] = fmaf(a.w, w.z, acc[3][2]); acc[3][3] = fmaf(a.w, w.w, acc[3][3]);
        }
        __syncthreads();
    }

#pragma unroll
    for (int i = 0; i < 4; i++) {
        int t = t0 + 4 * tm + i;
#pragma unroll
        for (int jq = 0; jq < 4; jq++) {
            int n = n0 + 4 * tn + jq;
            int g = n >> 10, j = n & 1023;
            int m = ((j >> 3) << 5) + ((j & 7) << 2) + g;
            float bias = __ldg(bi + n) + __ldg(bh + n);
            g_gx[(size_t)t * (G4_ * B_) + (size_t)m * B_ + b] = acc[i][jq] + bias;
        }
    }
}

// ---------------------------------------------------------------------------
// Phase 2: persistent mma.sync recurrence.
// Block: D[32,64] = W[32,1024] @ h[64,1024]^T.  Warp (mt = w&1, nh = w>>2? no:
// mt = w&1 picks m16 tile, nh = w>>1 picks 16-batch slice (2 n8 tiles).
// ---------------------------------------------------------------------------
extern __shared__ __align__(16) char smem2c[];

__global__ void __launch_bounds__(THREADS2, 1)
lstm_mma_kernel(float* __restrict__ out) {
    const int tid  = threadIdx.x;
    const int wid  = tid >> 5;
    const int lane = tid & 31;
    const int bid  = blockIdx.x;
    const int mt   = wid & 1;
    const int nh   = wid >> 1;
    const int gid  = lane >> 2;
    const int tig  = lane & 3;

    uint4* Ws4 = (uint4*)(smem2c + OFF_W);
    uint4* Hb4 = (uint4*)(smem2c + OFF_HB);
    float* Dsm = (float*)(smem2c + OFF_DSM);   // [32][66]
    const uint32_t hb_sa = smem_u32(smem2c + OFF_HB);

    float* Q  = out;
    float* hT = out + (size_t)B_ * T_ * HD_;
    float* cT = hT + (size_t)B_ * HD_;

    // load W fragments (64 KB) once
    {
        const uint4* wsrc = g_wpack + (size_t)bid * 4096;
        for (int i = tid; i < 4096; i += THREADS2) Ws4[i] = wsrc[i];
    }

    // epilogue mapping: thread -> (jl, batches bb, bb+1)
    const int jl = tid >> 5;
    const int bb = (tid & 31) * 2;
    const int jg = bid * 8 + jl;
    // h-fragment u16 slot for (jg, bb); slot for bb+1 is +32
    const int ks_  = jg >> 4;
    const int r_   = jg & 15;
    const int slot = (r_ >> 3) & 1;
    const int tg_  = (r_ & 7) >> 1;
    const int hw_  = r_ & 1;
    const int nh_  = bb >> 4;
    const int nt_  = (bb >> 3) & 1;
    const int gd_  = bb & 7;
    const int hidx = ((((ks_ * 4 + nh_) * 32 + gd_ * 4 + tg_) * 4) + nt_ * 2 + slot) * 2 + hw_;

    float cs0 = 0.0f, cs1 = 0.0f;
    __syncthreads();

    for (int t = 0; t < T_; t++) {
        if (t > 0) {
            float a0c[4] = {0.f, 0.f, 0.f, 0.f};
            float a1c[4] = {0.f, 0.f, 0.f, 0.f};
            const uint4* hsrc = g_hfrag[(t - 1) & 1];

            // prologue: stage chunk 0 into buf 0
            for (int i = tid; i < 2048; i += THREADS2)
                cp_async16(hb_sa + i * 16, hsrc + i);
            cp_commit();

#pragma unroll
            for (int c = 0; c < 4; c++) {
                if (c < 3) {
                    const uint4* s = hsrc + (c + 1) * 2048;
                    uint32_t d = hb_sa + ((c + 1) & 1) * 32768;
                    for (int i = tid; i < 2048; i += THREADS2)
                        cp_async16(d + i * 16, s + i);
                    cp_commit();
                    cp_wait1();
                } else {
                    cp_wait0();
                }
                __syncthreads();

                const uint4* Wk = Ws4 + (mt * 64 + c * 16) * 32 + lane;
                const uint4* Hk = Hb4 + ((c & 1) ? 2048 : 0) + nh * 32 + lane;
#pragma unroll
                for (int ksl = 0; ksl < 16; ksl++) {
                    uint4 a = Wk[ksl * 32];
                    uint4 b = Hk[ksl * 128];
                    mma16816(a0c[0], a0c[1], a0c[2], a0c[3], a.x, a.y, a.z, a.w, b.x, b.y);
                    mma16816(a1c[0], a1c[1], a1c[2], a1c[3], a.x, a.y, a.z, a.w, b.z, b.w);
                }
                __syncthreads();
            }

            // stage D to SMEM for gate-grouped epilogue
            {
                int row = mt * 16 + gid;
                int col = nh * 16 + tig * 2;
                *(float2*)&Dsm[row * 66 + col]           = make_float2(a0c[0], a0c[1]);
                *(float2*)&Dsm[(row + 8) * 66 + col]     = make_float2(a0c[2], a0c[3]);
                *(float2*)&Dsm[row * 66 + col + 8]       = make_float2(a1c[0], a1c[1]);
                *(float2*)&Dsm[(row + 8) * 66 + col + 8] = make_float2(a1c[2], a1c[3]);
            }
            __syncthreads();
        }

        // ---------------- epilogue ----------------
        {
            float pre[4][2];
            const float* gxp = g_gx + ((size_t)t * G4_ + (size_t)(bid * 32 + jl * 4)) * B_;
#pragma unroll
            for (int g = 0; g < 4; g++) {
                float2 u = *(const float2*)(gxp + (size_t)g * B_ + bb);
                pre[g][0] = u.x; pre[g][1] = u.y;
            }
            if (t > 0) {
#pragma unroll
                for (int g = 0; g < 4; g++) {
                    float2 d = *(const float2*)&Dsm[(jl * 4 + g) * 66 + bb];
                    pre[g][0] += d.x; pre[g][1] += d.y;
                }
            }
            unsigned short* hdst = (unsigned short*)g_hfrag[t & 1];
            {
                float f = sigf(pre[0][0]), ig = sigf(pre[1][0]);
                float a = tanhfa(pre[2][0]), o = sigf(pre[3][0]);
                cs0 = f * cs0 + ig * a;
                float h = o * tanhfa(cs0);
                Q[((long)bb * T_ + t) * HD_ + jg] = h;
                hdst[hidx] = __half_as_ushort(__float2half_rn(h));
                if (t == T_ - 1) { hT[(long)bb * HD_ + jg] = h; cT[(long)bb * HD_ + jg] = cs0; }
            }
            {
                float f = sigf(pre[0][1]), ig = sigf(pre[1][1]);
                float a = tanhfa(pre[2][1]), o = sigf(pre[3][1]);
                cs1 = f * cs1 + ig * a;
                float h = o * tanhfa(cs1);
                Q[((long)(bb + 1) * T_ + t) * HD_ + jg] = h;
                hdst[hidx + 32] = __half_as_ushort(__float2half_rn(h));
                if (t == T_ - 1) { hT[(long)(bb + 1) * HD_ + jg] = h; cT[(long)(bb + 1) * HD_ + jg] = cs1; }
            }
        }
        grid_barrier();
    }
}

// ---------------------------------------------------------------------------
extern "C" void kernel_launch(void* const* d_in, const int* in_sizes, int n_in,
                              void* d_out, int out_size) {
    (void)in_sizes; (void)n_in; (void)out_size;
    const float* x  = (const float*)d_in[0];
    const float* Wi = (const float*)d_in[1];
    const float* bi = (const float*)d_in[2];
    const float* Wh = (const float*)d_in[3];
    const float* bh = (const float*)d_in[4];
    float* out = (float*)d_out;

    cudaFuncSetAttribute(lstm_mma_kernel,
                         cudaFuncAttributeMaxDynamicSharedMemorySize, SMEM2);

    pack_w_kernel<<<dim3(NBLK, 64), 64>>>(Wh);
    dim3 g1(G4_ / 64, T_ / 64, B_);
    gemm_x_kernel<<<g1, 256>>>(x, Wi, bi, bh);
    lstm_mma_kernel<<<NBLK, THREADS2, SMEM2>>>(out);
}

// round 10
// speedup vs baseline: 8.5592x; 1.9612x over previous
#include <cuda_runtime.h>
#include <cuda_fp16.h>
#include <math.h>
#include <stdint.h>

#define B_   64
#define T_   256
#define ID_  512
#define HD_  1024
#define G4_  4096

#define NBLK     128
#define THREADS2 256

// phase-2 SMEM layout (dynamic)
#define OFF_W    0                      // 4096 uint4 = 64 KB (A fragments)
#define OFF_HB   65536                  // 2 x 2048 uint4 = 64 KB (B fragment chunks)
#define OFF_DSM  131072                 // 32 x 66 floats = 8448 B
#define SMEM2    (OFF_DSM + 32*66*4)    // 139520

// phase-1 GEMM smem: 2 stages x (A 16KB + B 16KB)
#define SMEMG    65536

// g_gx layout: [t][b][m4], m4 = 4*j + g   (256 MB)
__device__ float g_gx[(size_t)T_ * B_ * G4_];
__device__ uint4 g_wpack[(size_t)NBLK * 4096];       // phase-2 A-fragment images (8 MB)
__device__ uint4 g_hfrag[2][8192];                   // phase-2 B-fragment images
__device__ uint4 g_xfrag[(size_t)1024 * 32 * 32];    // phase-1 A fragments (16 MB)
__device__ uint2 g_wifrag[(size_t)512 * 32 * 32];    // phase-1 B fragments (4 MB)
__device__ float g_biaspk[G4_];                      // bias in m4 order
__device__ unsigned int g_bar_count = 0;
__device__ unsigned int g_bar_gen   = 0;

// ---------------- helpers ----------------------------------------------------
__device__ __forceinline__ uint32_t smem_u32(const void* p) {
    uint32_t a;
    asm("{ .reg .u64 t; cvta.to.shared.u64 t, %1; cvt.u32.u64 %0, t; }" : "=r"(a) : "l"(p));
    return a;
}
__device__ __forceinline__ void cp_async16(uint32_t dst, const void* src) {
    asm volatile("cp.async.cg.shared.global [%0], [%1], 16;" :: "r"(dst), "l"(src) : "memory");
}
__device__ __forceinline__ void cp_commit() { asm volatile("cp.async.commit_group;" ::: "memory"); }
__device__ __forceinline__ void cp_wait1()  { asm volatile("cp.async.wait_group 1;" ::: "memory"); }
__device__ __forceinline__ void cp_wait0()  { asm volatile("cp.async.wait_group 0;" ::: "memory"); }

__device__ __forceinline__ void mma16816(float& d0, float& d1, float& d2, float& d3,
                                         uint32_t a0, uint32_t a1, uint32_t a2, uint32_t a3,
                                         uint32_t b0, uint32_t b1) {
    asm volatile(
        "mma.sync.aligned.m16n8k16.row.col.f32.f16.f16.f32 "
        "{%0,%1,%2,%3}, {%4,%5,%6,%7}, {%8,%9}, {%0,%1,%2,%3};"
        : "+f"(d0), "+f"(d1), "+f"(d2), "+f"(d3)
        : "r"(a0), "r"(a1), "r"(a2), "r"(a3), "r"(b0), "r"(b1));
}
__device__ __forceinline__ uint32_t f2h2(float lo, float hi) {
    __half2 h = __floats2half2_rn(lo, hi);
    return *(uint32_t*)&h;
}
__device__ __forceinline__ float sigf(float x)   { return __fdividef(1.0f, 1.0f + __expf(-x)); }
__device__ __forceinline__ float tanhfa(float x) { return fmaf(2.0f, sigf(2.0f * x), -1.0f); }

__device__ __forceinline__ void grid_barrier() {
    __syncthreads();
    if (threadIdx.x == 0) {
        __threadfence();
        unsigned gen = atomicAdd(&g_bar_gen, 0u);
        unsigned arrived = atomicAdd(&g_bar_count, 1u);
        if (arrived == NBLK - 1) {
            atomicExch(&g_bar_count, 0u);
            __threadfence();
            atomicAdd(&g_bar_gen, 1u);
        } else {
            while (atomicAdd(&g_bar_gen, 0u) == gen) { __nanosleep(64); }
        }
        __threadfence();
    }
    __syncthreads();
}

// ---------------------------------------------------------------------------
// Pack Wh into per-block phase-2 A-fragment images (verified layout).
// ---------------------------------------------------------------------------
__global__ void pack_w_kernel(const float* __restrict__ Wh) {
    int bid = blockIdx.x, ks = blockIdx.y;
    int tid = threadIdx.x;          // 64 threads
    int mt = tid >> 5, lane = tid & 31;
    int gid = lane >> 2, tig = lane & 3;

    int r0 = mt * 16 + gid;
    int r1 = r0 + 8;
    int c0 = ((r0 & 3) << 10) + bid * 8 + (r0 >> 2);
    int c1 = ((r1 & 3) << 10) + bid * 8 + (r1 >> 2);
    int k0 = ks * 16 + tig * 2;

    const float* W0 = Wh + c0;
    const float* W1 = Wh + c1;
    uint4 v;
    v.x = f2h2(W0[(size_t)k0 * G4_],       W0[(size_t)(k0 + 1) * G4_]);
    v.y = f2h2(W1[(size_t)k0 * G4_],       W1[(size_t)(k0 + 1) * G4_]);
    v.z = f2h2(W0[(size_t)(k0 + 8) * G4_], W0[(size_t)(k0 + 9) * G4_]);
    v.w = f2h2(W1[(size_t)(k0 + 8) * G4_], W1[(size_t)(k0 + 9) * G4_]);
    g_wpack[(size_t)bid * 4096 + ((mt * 64 + ks) * 32 + lane)] = v;
}

// ---------------------------------------------------------------------------
// Pack x into phase-1 A fragments: x rows r = b*T+t (flat), cols k.
// g_xfrag[(mt*32 + ks)*32 + lane]
// ---------------------------------------------------------------------------
__global__ void pack_x_kernel(const float* __restrict__ x) {
    int mt = blockIdx.x;                       // 0..1023
    int w  = threadIdx.x >> 5;
    int ks = blockIdx.y * 8 + w;               // 0..31
    int lane = threadIdx.x & 31;
    int gid = lane >> 2, tig = lane & 3;

    int r0 = mt * 16 + gid;
    int k0 = ks * 16 + tig * 2;
    const float* X0 = x + (size_t)r0 * ID_;
    const float* X1 = X0 + 8 * ID_;
    uint4 v;
    v.x = f2h2(X0[k0],     X0[k0 + 1]);
    v.y = f2h2(X1[k0],     X1[k0 + 1]);
    v.z = f2h2(X0[k0 + 8], X0[k0 + 9]);
    v.w = f2h2(X1[k0 + 8], X1[k0 + 9]);
    g_xfrag[((size_t)mt * 32 + ks) * 32 + lane] = v;
}

// ---------------------------------------------------------------------------
// Pack Wi into phase-1 B fragments with the (g,j)-gather column order:
// packed col P -> n = (P&3)*1024 + (P>>2).   g_wifrag[(nt*32+ks)*32+lane]
// ---------------------------------------------------------------------------
__global__ void pack_wi_kernel(const float* __restrict__ Wi) {
    int nt = blockIdx.x;                       // 0..511 (p-tile of 8)
    int w  = threadIdx.x >> 5;
    int ks = blockIdx.y * 8 + w;
    int lane = threadIdx.x & 31;
    int gid = lane >> 2, tig = lane & 3;

    int P = nt * 8 + gid;
    int n = ((P & 3) << 10) + (P >> 2);
    int k0 = ks * 16 + tig * 2;
    const float* W = Wi + n;
    uint2 v;
    v.x = f2h2(W[(size_t)k0 * G4_],       W[(size_t)(k0 + 1) * G4_]);
    v.y = f2h2(W[(size_t)(k0 + 8) * G4_], W[(size_t)(k0 + 9) * G4_]);
    g_wifrag[((size_t)nt * 32 + ks) * 32 + lane] = v;
}

__global__ void pack_bias_kernel(const float* __restrict__ bi,
                                 const float* __restrict__ bh) {
    int m4 = blockIdx.x * 256 + threadIdx.x;
    int n = ((m4 & 3) << 10) + (m4 >> 2);
    g_biaspk[m4] = bi[n] + bh[n];
}

// ---------------------------------------------------------------------------
// Phase 1: tensor-core GEMM.  D[r, P] = sum_k x[r,k] * Wi[k, n(P)] + bias
// grid (128 mblk, 32 jb); block 256 (8 warps = 2 m-rows x 4 n-cols).
// Output to g_gx[t][b][jb*128 + P].
// ---------------------------------------------------------------------------
extern __shared__ __align__(16) char gsm[];

__global__ void __launch_bounds__(256)
gemm_x_mma(void) {
    const int tid  = threadIdx.x;
    const int wid  = tid >> 5;
    const int lane = tid & 31;
    const int gid  = lane >> 2;
    const int tig  = lane & 3;
    const int mblk = blockIdx.x;
    const int jb   = blockIdx.y;
    const int mrow = wid & 1;
    const int ncol = wid >> 1;

    float acc[4][4][4];
#pragma unroll
    for (int mi = 0; mi < 4; mi++)
#pragma unroll
        for (int ni = 0; ni < 4; ni++)
#pragma unroll
            for (int q = 0; q < 4; q++) acc[mi][ni][q] = 0.0f;

    const uint32_t sa = smem_u32(gsm);
    const char* asrc = (const char*)(g_xfrag + (size_t)mblk * 8 * 32 * 32);
    const char* bsrc = (const char*)(g_wifrag + (size_t)jb * 16 * 32 * 32);

    // copy one stage (4 k-slabs): A runs of 2KB per mt, B runs of 1KB per nt
    auto copy_stage = [&](int kc, int buf) {
        uint32_t base = sa + buf * 32768;
        int ks0 = kc * 4;
#pragma unroll
        for (int q = 0; q < 4; q++) {
            int idx = q * 256 + tid;            // 0..1023
            int mtl = idx >> 7, off = idx & 127;
            cp_async16(base + mtl * 2048 + off * 16,
                       asrc + ((size_t)(mtl * 32 + ks0) * 32) * 16 + off * 16);
        }
#pragma unroll
        for (int q = 0; q < 4; q++) {
            int idx = q * 256 + tid;
            int ntl = idx >> 6, off = idx & 63;  // off in 16B units
            cp_async16(base + 16384 + ntl * 1024 + off * 16,
                       bsrc + ((size_t)(ntl * 32 + ks0) * 32) * 8 + off * 16);
        }
        cp_commit();
    };

    copy_stage(0, 0);
#pragma unroll 1
    for (int kc = 0; kc < 8; kc++) {
        if (kc < 7) { copy_stage(kc + 1, (kc + 1) & 1); cp_wait1(); }
        else        { cp_wait0(); }
        __syncthreads();

        const uint4* Asm = (const uint4*)(gsm + (kc & 1) * 32768);
        const uint2* Bsm = (const uint2*)(gsm + (kc & 1) * 32768 + 16384);
#pragma unroll
        for (int ksl = 0; ksl < 4; ksl++) {
            uint4 a[4];
            uint2 b[4];
#pragma unroll
            for (int mi = 0; mi < 4; mi++)
                a[mi] = Asm[(mrow * 4 + mi) * 128 + ksl * 32 + lane];
#pragma unroll
            for (int ni = 0; ni < 4; ni++)
                b[ni] = Bsm[(ncol * 4 + ni) * 128 + ksl * 32 + lane];
#pragma unroll
            for (int mi = 0; mi < 4; mi++)
#pragma unroll
                for (int ni = 0; ni < 4; ni++)
                    mma16816(acc[mi][ni][0], acc[mi][ni][1], acc[mi][ni][2], acc[mi][ni][3],
                             a[mi].x, a[mi].y, a[mi].z, a[mi].w, b[ni].x, b[ni].y);
        }
        __syncthreads();
    }

    // epilogue: add bias, store float2 pairs to g_gx[t][b][m4]
    float2 bias[4];
#pragma unroll
    for (int ni = 0; ni < 4; ni++)
        bias[ni] = *(const float2*)(g_biaspk + jb * 128 + ncol * 32 + ni * 8 + 2 * tig);

#pragma unroll
    for (int mi = 0; mi < 4; mi++) {
        int r0 = mblk * 128 + mrow * 64 + mi * 16 + gid;
        int t0 = r0 & (T_ - 1), b0r = r0 >> 8;
        size_t base0 = (size_t)t0 * (B_ * G4_) + (size_t)b0r * G4_ + jb * 128;
        size_t base1 = base0 + 8 * (size_t)(B_ * G4_);   // row r0+8: t0+8, same b
#pragma unroll
        for (int ni = 0; ni < 4; ni++) {
            int p = ncol * 32 + ni * 8 + 2 * tig;
            *(float2*)(g_gx + base0 + p) =
                make_float2(acc[mi][ni][0] + bias[ni].x, acc[mi][ni][1] + bias[ni].y);
            *(float2*)(g_gx + base1 + p) =
                make_float2(acc[mi][ni][2] + bias[ni].x, acc[mi][ni][3] + bias[ni].y);
        }
    }
}

// ---------------------------------------------------------------------------
// Phase 2: persistent mma.sync recurrence (unchanged except gx read layout).
// ---------------------------------------------------------------------------
extern __shared__ __align__(16) char smem2c[];

__global__ void __launch_bounds__(THREADS2, 1)
lstm_mma_kernel(float* __restrict__ out) {
    const int tid  = threadIdx.x;
    const int wid  = tid >> 5;
    const int lane = tid & 31;
    const int bid  = blockIdx.x;
    const int mt   = wid & 1;
    const int nh   = wid >> 1;
    const int gid  = lane >> 2;
    const int tig  = lane & 3;

    uint4* Ws4 = (uint4*)(smem2c + OFF_W);
    uint4* Hb4 = (uint4*)(smem2c + OFF_HB);
    float* Dsm = (float*)(smem2c + OFF_DSM);   // [32][66]
    const uint32_t hb_sa = smem_u32(smem2c + OFF_HB);

    float* Q  = out;
    float* hT = out + (size_t)B_ * T_ * HD_;
    float* cT = hT + (size_t)B_ * HD_;

    {
        const uint4* wsrc = g_wpack + (size_t)bid * 4096;
        for (int i = tid; i < 4096; i += THREADS2) Ws4[i] = wsrc[i];
    }

    const int jl = tid >> 5;
    const int bb = (tid & 31) * 2;
    const int jg = bid * 8 + jl;
    const int ks_  = jg >> 4;
    const int r_   = jg & 15;
    const int slot = (r_ >> 3) & 1;
    const int tg_  = (r_ & 7) >> 1;
    const int hw_  = r_ & 1;
    const int nh_  = bb >> 4;
    const int nt_  = (bb >> 3) & 1;
    const int gd_  = bb & 7;
    const int hidx = ((((ks_ * 4 + nh_) * 32 + gd_ * 4 + tg_) * 4) + nt_ * 2 + slot) * 2 + hw_;

    float cs0 = 0.0f, cs1 = 0.0f;
    __syncthreads();

    for (int t = 0; t < T_; t++) {
        if (t > 0) {
            float a0c[4] = {0.f, 0.f, 0.f, 0.f};
            float a1c[4] = {0.f, 0.f, 0.f, 0.f};
            const uint4* hsrc = g_hfrag[(t - 1) & 1];

            for (int i = tid; i < 2048; i += THREADS2)
                cp_async16(hb_sa + i * 16, hsrc + i);
            cp_commit();

#pragma unroll
            for (int c = 0; c < 4; c++) {
                if (c < 3) {
                    const uint4* s = hsrc + (c + 1) * 2048;
                    uint32_t d = hb_sa + ((c + 1) & 1) * 32768;
                    for (int i = tid; i < 2048; i += THREADS2)
                        cp_async16(d + i * 16, s + i);
                    cp_commit();
                    cp_wait1();
                } else {
                    cp_wait0();
                }
                __syncthreads();

                const uint4* Wk = Ws4 + (mt * 64 + c * 16) * 32 + lane;
                const uint4* Hk = Hb4 + ((c & 1) ? 2048 : 0) + nh * 32 + lane;
#pragma unroll
                for (int ksl = 0; ksl < 16; ksl++) {
                    uint4 a = Wk[ksl * 32];
                    uint4 b = Hk[ksl * 128];
                    mma16816(a0c[0], a0c[1], a0c[2], a0c[3], a.x, a.y, a.z, a.w, b.x, b.y);
                    mma16816(a1c[0], a1c[1], a1c[2], a1c[3], a.x, a.y, a.z, a.w, b.z, b.w);
                }
                __syncthreads();
            }

            {
                int row = mt * 16 + gid;
                int col = nh * 16 + tig * 2;
                *(float2*)&Dsm[row * 66 + col]           = make_float2(a0c[0], a0c[1]);
                *(float2*)&Dsm[(row + 8) * 66 + col]     = make_float2(a0c[2], a0c[3]);
                *(float2*)&Dsm[row * 66 + col + 8]       = make_float2(a1c[0], a1c[1]);
                *(float2*)&Dsm[(row + 8) * 66 + col + 8] = make_float2(a1c[2], a1c[3]);
            }
            __syncthreads();
        }

        // ---------------- epilogue ----------------
        {
            // gx read: [t][b][m4] with m4 = 4*jg + g  -> one float4 per batch
            const float* gxp = g_gx + (size_t)t * (B_ * G4_) + (size_t)bb * G4_ + jg * 4;
            float4 u = *(const float4*)gxp;
            float4 v = *(const float4*)(gxp + G4_);
            float pre[4][2];
            pre[0][0] = u.x; pre[1][0] = u.y; pre[2][0] = u.z; pre[3][0] = u.w;
            pre[0][1] = v.x; pre[1][1] = v.y; pre[2][1] = v.z; pre[3][1] = v.w;
            if (t > 0) {
#pragma unroll
                for (int g = 0; g < 4; g++) {
                    float2 d = *(const float2*)&Dsm[(jl * 4 + g) * 66 + bb];
                    pre[g][0] += d.x; pre[g][1] += d.y;
                }
            }
            unsigned short* hdst = (unsigned short*)g_hfrag[t & 1];
            {
                float f = sigf(pre[0][0]), ig = sigf(pre[1][0]);
                float a = tanhfa(pre[2][0]), o = sigf(pre[3][0]);
                cs0 = f * cs0 + ig * a;
                float h = o * tanhfa(cs0);
                Q[((long)bb * T_ + t) * HD_ + jg] = h;
                hdst[hidx] = __half_as_ushort(__float2half_rn(h));
                if (t == T_ - 1) { hT[(long)bb * HD_ + jg] = h; cT[(long)bb * HD_ + jg] = cs0; }
            }
            {
                float f = sigf(pre[0][1]), ig = sigf(pre[1][1]);
                float a = tanhfa(pre[2][1]), o = sigf(pre[3][1]);
                cs1 = f * cs1 + ig * a;
                float h = o * tanhfa(cs1);
                Q[((long)(bb + 1) * T_ + t) * HD_ + jg] = h;
                hdst[hidx + 32] = __half_as_ushort(__float2half_rn(h));
                if (t == T_ - 1) { hT[(long)(bb + 1) * HD_ + jg] = h; cT[(long)(bb + 1) * HD_ + jg] = cs1; }
            }
        }
        grid_barrier();
    }
}

// ---------------------------------------------------------------------------
extern "C" void kernel_launch(void* const* d_in, const int* in_sizes, int n_in,
                              void* d_out, int out_size) {
    (void)in_sizes; (void)n_in; (void)out_size;
    const float* x  = (const float*)d_in[0];
    const float* Wi = (const float*)d_in[1];
    const float* bi = (const float*)d_in[2];
    const float* Wh = (const float*)d_in[3];
    const float* bh = (const float*)d_in[4];
    float* out = (float*)d_out;

    cudaFuncSetAttribute(lstm_mma_kernel,
                         cudaFuncAttributeMaxDynamicSharedMemorySize, SMEM2);
    cudaFuncSetAttribute(gemm_x_mma,
                         cudaFuncAttributeMaxDynamicSharedMemorySize, SMEMG);

    pack_w_kernel<<<dim3(NBLK, 64), 64>>>(Wh);
    pack_x_kernel<<<dim3(1024, 4), 256>>>(x);
    pack_wi_kernel<<<dim3(512, 4), 256>>>(Wi);
    pack_bias_kernel<<<16, 256>>>(bi, bh);
    gemm_x_mma<<<dim3(128, 32), 256, SMEMG>>>();
    lstm_mma_kernel<<<NBLK, THREADS2, SMEM2>>>(out);
}

// round 13
// speedup vs baseline: 9.2410x; 1.0797x over previous
#include <cuda_runtime.h>
#include <cuda_fp16.h>
#include <math.h>
#include <stdint.h>

#define B_   64
#define T_   256
#define ID_  512
#define HD_  1024
#define G4_  4096

#define NBLK     128
#define THREADS2 256

// phase-2 SMEM: W fragments (64 KB) + D staging
#define OFF_W    0
#define OFF_DSM  65536
#define SMEM2    (OFF_DSM + 32*66*4)    // 74016 -> pad
// phase-1 GEMM smem: 2 stages x (A 16KB + B 16KB)
#define SMEMG    65536

// g_gx layout: [t][b][m4], m4 = 4*j + g   (256 MB)
__device__ float g_gx[(size_t)T_ * B_ * G4_];
__device__ uint4 g_wpack[(size_t)NBLK * 4096];       // phase-2 A-fragment images (8 MB)
__device__ uint4 g_hfrag[2][8192];                   // phase-2 B-fragment images
__device__ uint4 g_xfrag[(size_t)1024 * 32 * 32];    // phase-1 A fragments (16 MB)
__device__ uint2 g_wifrag[(size_t)512 * 32 * 32];    // phase-1 B fragments (4 MB)
__device__ float g_biaspk[G4_];                      // bias in m4 order
__device__ unsigned int g_bar_count = 0;
__device__ unsigned int g_bar_gen   = 0;

// ---------------- helpers ----------------------------------------------------
__device__ __forceinline__ uint32_t smem_u32(const void* p) {
    uint32_t a;
    asm("{ .reg .u64 t; cvta.to.shared.u64 t, %1; cvt.u32.u64 %0, t; }" : "=r"(a) : "l"(p));
    return a;
}
__device__ __forceinline__ void cp_async16(uint32_t dst, const void* src) {
    asm volatile("cp.async.cg.shared.global [%0], [%1], 16;" :: "r"(dst), "l"(src) : "memory");
}
__device__ __forceinline__ void cp_commit() { asm volatile("cp.async.commit_group;" ::: "memory"); }
__device__ __forceinline__ void cp_wait1()  { asm volatile("cp.async.wait_group 1;" ::: "memory"); }
__device__ __forceinline__ void cp_wait0()  { asm volatile("cp.async.wait_group 0;" ::: "memory"); }

__device__ __forceinline__ void mma16816(float& d0, float& d1, float& d2, float& d3,
                                         uint32_t a0, uint32_t a1, uint32_t a2, uint32_t a3,
                                         uint32_t b0, uint32_t b1) {
    asm volatile(
        "mma.sync.aligned.m16n8k16.row.col.f32.f16.f16.f32 "
        "{%0,%1,%2,%3}, {%4,%5,%6,%7}, {%8,%9}, {%0,%1,%2,%3};"
        : "+f"(d0), "+f"(d1), "+f"(d2), "+f"(d3)
        : "r"(a0), "r"(a1), "r"(a2), "r"(a3), "r"(b0), "r"(b1));
}
__device__ __forceinline__ uint32_t f2h2(float lo, float hi) {
    __half2 h = __floats2half2_rn(lo, hi);
    return *(uint32_t*)&h;
}
__device__ __forceinline__ uint4 ldcg4(const uint4* p) {
    uint4 v;
    asm volatile("ld.global.cg.v4.u32 {%0,%1,%2,%3}, [%4];"
                 : "=r"(v.x), "=r"(v.y), "=r"(v.z), "=r"(v.w) : "l"(p));
    return v;
}
__device__ __forceinline__ float sigf(float x)   { return __fdividef(1.0f, 1.0f + __expf(-x)); }
__device__ __forceinline__ float tanhfa(float x) { return fmaf(2.0f, sigf(2.0f * x), -1.0f); }

// grid barrier: arrive by atomic, poll by plain acquire loads (no RMW serialization)
__device__ __forceinline__ void grid_barrier() {
    __syncthreads();
    if (threadIdx.x == 0) {
        unsigned gen;
        asm volatile("ld.acquire.gpu.global.b32 %0, [%1];" : "=r"(gen) : "l"(&g_bar_gen));
        __threadfence();
        unsigned arrived = atomicAdd(&g_bar_count, 1u);
        if (arrived == NBLK - 1) {
            atomicExch(&g_bar_count, 0u);
            __threadfence();
            atomicAdd(&g_bar_gen, 1u);
        } else {
            unsigned g2;
            do {
                asm volatile("ld.acquire.gpu.global.b32 %0, [%1];" : "=r"(g2) : "l"(&g_bar_gen));
            } while (g2 == gen);
        }
        __threadfence();
    }
    __syncthreads();
}

// ---------------------------------------------------------------------------
// Pack Wh into per-block phase-2 A-fragment images (verified layout).
// ---------------------------------------------------------------------------
__global__ void pack_w_kernel(const float* __restrict__ Wh) {
    int bid = blockIdx.x, ks = blockIdx.y;
    int tid = threadIdx.x;          // 64 threads
    int mt = tid >> 5, lane = tid & 31;
    int gid = lane >> 2, tig = lane & 3;

    int r0 = mt * 16 + gid;
    int r1 = r0 + 8;
    int c0 = ((r0 & 3) << 10) + bid * 8 + (r0 >> 2);
    int c1 = ((r1 & 3) << 10) + bid * 8 + (r1 >> 2);
    int k0 = ks * 16 + tig * 2;

    const float* W0 = Wh + c0;
    const float* W1 = Wh + c1;
    uint4 v;
    v.x = f2h2(W0[(size_t)k0 * G4_],       W0[(size_t)(k0 + 1) * G4_]);
    v.y = f2h2(W1[(size_t)k0 * G4_],       W1[(size_t)(k0 + 1) * G4_]);
    v.z = f2h2(W0[(size_t)(k0 + 8) * G4_], W0[(size_t)(k0 + 9) * G4_]);
    v.w = f2h2(W1[(size_t)(k0 + 8) * G4_], W1[(size_t)(k0 + 9) * G4_]);
    g_wpack[(size_t)bid * 4096 + ((mt * 64 + ks) * 32 + lane)] = v;
}

// ---------------------------------------------------------------------------
// Pack x into phase-1 A fragments.
// ---------------------------------------------------------------------------
__global__ void pack_x_kernel(const float* __restrict__ x) {
    int mt = blockIdx.x;
    int w  = threadIdx.x >> 5;
    int ks = blockIdx.y * 8 + w;
    int lane = threadIdx.x & 31;
    int gid = lane >> 2, tig = lane & 3;

    int r0 = mt * 16 + gid;
    int k0 = ks * 16 + tig * 2;
    const float* X0 = x + (size_t)r0 * ID_;
    const float* X1 = X0 + 8 * ID_;
    uint4 v;
    v.x = f2h2(X0[k0],     X0[k0 + 1]);
    v.y = f2h2(X1[k0],     X1[k0 + 1]);
    v.z = f2h2(X0[k0 + 8], X0[k0 + 9]);
    v.w = f2h2(X1[k0 + 8], X1[k0 + 9]);
    g_xfrag[((size_t)mt * 32 + ks) * 32 + lane] = v;
}

// ---------------------------------------------------------------------------
// Pack Wi into phase-1 B fragments: packed col P -> n = (P&3)*1024 + (P>>2).
// ---------------------------------------------------------------------------
__global__ void pack_wi_kernel(const float* __restrict__ Wi) {
    int nt = blockIdx.x;
    int w  = threadIdx.x >> 5;
    int ks = blockIdx.y * 8 + w;
    int lane = threadIdx.x & 31;
    int gid = lane >> 2, tig = lane & 3;

    int P = nt * 8 + gid;
    int n = ((P & 3) << 10) + (P >> 2);
    int k0 = ks * 16 + tig * 2;
    const float* W = Wi + n;
    uint2 v;
    v.x = f2h2(W[(size_t)k0 * G4_],       W[(size_t)(k0 + 1) * G4_]);
    v.y = f2h2(W[(size_t)(k0 + 8) * G4_], W[(size_t)(k0 + 9) * G4_]);
    g_wifrag[((size_t)nt * 32 + ks) * 32 + lane] = v;
}

__global__ void pack_bias_kernel(const float* __restrict__ bi,
                                 const float* __restrict__ bh) {
    int m4 = blockIdx.x * 256 + threadIdx.x;
    int n = ((m4 & 3) << 10) + (m4 >> 2);
    g_biaspk[m4] = bi[n] + bh[n];
}

// ---------------------------------------------------------------------------
// Phase 1: tensor-core GEMM -> g_gx[t][b][m4]
// ---------------------------------------------------------------------------
extern __shared__ __align__(16) char gsm[];

__global__ void __launch_bounds__(256)
gemm_x_mma(void) {
    const int tid  = threadIdx.x;
    const int wid  = tid >> 5;
    const int lane = tid & 31;
    const int gid  = lane >> 2;
    const int tig  = lane & 3;
    const int mblk = blockIdx.x;
    const int jb   = blockIdx.y;
    const int mrow = wid & 1;
    const int ncol = wid >> 1;

    float acc[4][4][4];
#pragma unroll
    for (int mi = 0; mi < 4; mi++)
#pragma unroll
        for (int ni = 0; ni < 4; ni++)
#pragma unroll
            for (int q = 0; q < 4; q++) acc[mi][ni][q] = 0.0f;

    const uint32_t sa = smem_u32(gsm);
    const char* asrc = (const char*)(g_xfrag + (size_t)mblk * 8 * 32 * 32);
    const char* bsrc = (const char*)(g_wifrag + (size_t)jb * 16 * 32 * 32);

    auto copy_stage = [&](int kc, int buf) {
        uint32_t base = sa + buf * 32768;
        int ks0 = kc * 4;
#pragma unroll
        for (int q = 0; q < 4; q++) {
            int idx = q * 256 + tid;
            int mtl = idx >> 7, off = idx & 127;
            cp_async16(base + mtl * 2048 + off * 16,
                       asrc + ((size_t)(mtl * 32 + ks0) * 32) * 16 + off * 16);
        }
#pragma unroll
        for (int q = 0; q < 4; q++) {
            int idx = q * 256 + tid;
            int ntl = idx >> 6, off = idx & 63;
            cp_async16(base + 16384 + ntl * 1024 + off * 16,
                       bsrc + ((size_t)(ntl * 32 + ks0) * 32) * 8 + off * 16);
        }
        cp_commit();
    };

    copy_stage(0, 0);
#pragma unroll 1
    for (int kc = 0; kc < 8; kc++) {
        if (kc < 7) { copy_stage(kc + 1, (kc + 1) & 1); cp_wait1(); }
        else        { cp_wait0(); }
        __syncthreads();

        const uint4* Asm = (const uint4*)(gsm + (kc & 1) * 32768);
        const uint2* Bsm = (const uint2*)(gsm + (kc & 1) * 32768 + 16384);
#pragma unroll
        for (int ksl = 0; ksl < 4; ksl++) {
            uint4 a[4];
            uint2 b[4];
#pragma unroll
            for (int mi = 0; mi < 4; mi++)
                a[mi] = Asm[(mrow * 4 + mi) * 128 + ksl * 32 + lane];
#pragma unroll
            for (int ni = 0; ni < 4; ni++)
                b[ni] = Bsm[(ncol * 4 + ni) * 128 + ksl * 32 + lane];
#pragma unroll
            for (int mi = 0; mi < 4; mi++)
#pragma unroll
                for (int ni = 0; ni < 4; ni++)
                    mma16816(acc[mi][ni][0], acc[mi][ni][1], acc[mi][ni][2], acc[mi][ni][3],
                             a[mi].x, a[mi].y, a[mi].z, a[mi].w, b[ni].x, b[ni].y);
        }
        __syncthreads();
    }

    float2 bias[4];
#pragma unroll
    for (int ni = 0; ni < 4; ni++)
        bias[ni] = *(const float2*)(g_biaspk + jb * 128 + ncol * 32 + ni * 8 + 2 * tig);

#pragma unroll
    for (int mi = 0; mi < 4; mi++) {
        int r0 = mblk * 128 + mrow * 64 + mi * 16 + gid;
        int t0 = r0 & (T_ - 1), b0r = r0 >> 8;
        size_t base0 = (size_t)t0 * (B_ * G4_) + (size_t)b0r * G4_ + jb * 128;
        size_t base1 = base0 + 8 * (size_t)(B_ * G4_);
#pragma unroll
        for (int ni = 0; ni < 4; ni++) {
            int p = ncol * 32 + ni * 8 + 2 * tig;
            *(float2*)(g_gx + base0 + p) =
                make_float2(acc[mi][ni][0] + bias[ni].x, acc[mi][ni][1] + bias[ni].y);
            *(float2*)(g_gx + base1 + p) =
                make_float2(acc[mi][ni][2] + bias[ni].x, acc[mi][ni][3] + bias[ni].y);
        }
    }
}

// ---------------------------------------------------------------------------
// Phase 2: persistent mma.sync recurrence. B fragments via ld.global.cg into a
// register double buffer (no SMEM staging, no per-chunk syncs).
// ---------------------------------------------------------------------------
extern __shared__ __align__(16) char smem2c[];

__global__ void __launch_bounds__(THREADS2, 1)
lstm_mma_kernel(float* __restrict__ out) {
    const int tid  = threadIdx.x;
    const int wid  = tid >> 5;
    const int lane = tid & 31;
    const int bid  = blockIdx.x;
    const int mt   = wid & 1;
    const int nh   = wid >> 1;
    const int gid  = lane >> 2;
    const int tig  = lane & 3;

    uint4* Ws4 = (uint4*)(smem2c + OFF_W);
    float* Dsm = (float*)(smem2c + OFF_DSM);   // [32][66]

    float* Q  = out;
    float* hT = out + (size_t)B_ * T_ * HD_;
    float* cT = hT + (size_t)B_ * HD_;

    {
        const uint4* wsrc = g_wpack + (size_t)bid * 4096;
        for (int i = tid; i < 4096; i += THREADS2) Ws4[i] = wsrc[i];
    }

    const int jl = tid >> 5;
    const int bb = (tid & 31) * 2;
    const int jg = bid * 8 + jl;
    const int ks_  = jg >> 4;
    const int r_   = jg & 15;
    const int slot = (r_ >> 3) & 1;
    const int tg_  = (r_ & 7) >> 1;
    const int hw_  = r_ & 1;
    const int nh_  = bb >> 4;
    const int nt_  = (bb >> 3) & 1;
    const int gd_  = bb & 7;
    const int hidx = ((((ks_ * 4 + nh_) * 32 + gd_ * 4 + tg_) * 4) + nt_ * 2 + slot) * 2 + hw_;

    float cs0 = 0.0f, cs1 = 0.0f;
    __syncthreads();

    for (int t = 0; t < T_; t++) {
        // prefetch this step's gx (gates-x) early
        const float* gxp = g_gx + (size_t)t * (B_ * G4_) + (size_t)bb * G4_ + jg * 4;
        float4 gu = *(const float4*)gxp;
        float4 gv = *(const float4*)(gxp + G4_);

        if (t > 0) {
            float a0c[4] = {0.f, 0.f, 0.f, 0.f};
            float a1c[4] = {0.f, 0.f, 0.f, 0.f};
            const uint4* hbase = g_hfrag[(t - 1) & 1] + nh * 32 + lane;

            uint4 ba[16], bbu[16];
#pragma unroll
            for (int k = 0; k < 16; k++) ba[k] = ldcg4(hbase + k * 128);

            // chunk 0 (load chunk 1 concurrently)
#pragma unroll
            for (int k = 0; k < 16; k++) bbu[k] = ldcg4(hbase + (16 + k) * 128);
            {
                const uint4* Wk = Ws4 + (mt * 64 + 0) * 32 + lane;
#pragma unroll
                for (int k = 0; k < 16; k++) {
                    uint4 a = Wk[k * 32];
                    mma16816(a0c[0], a0c[1], a0c[2], a0c[3], a.x, a.y, a.z, a.w, ba[k].x, ba[k].y);
                    mma16816(a1c[0], a1c[1], a1c[2], a1c[3], a.x, a.y, a.z, a.w, ba[k].z, ba[k].w);
                }
            }
            // chunk 1 (load chunk 2)
#pragma unroll
            for (int k = 0; k < 16; k++) ba[k] = ldcg4(hbase + (32 + k) * 128);
            {
                const uint4* Wk = Ws4 + (mt * 64 + 16) * 32 + lane;
#pragma unroll
                for (int k = 0; k < 16; k++) {
                    uint4 a = Wk[k * 32];
                    mma16816(a0c[0], a0c[1], a0c[2], a0c[3], a.x, a.y, a.z, a.w, bbu[k].x, bbu[k].y);
                    mma16816(a1c[0], a1c[1], a1c[2], a1c[3], a.x, a.y, a.z, a.w, bbu[k].z, bbu[k].w);
                }
            }
            // chunk 2 (load chunk 3)
#pragma unroll
            for (int k = 0; k < 16; k++) bbu[k] = ldcg4(hbase + (48 + k) * 128);
            {
                const uint4* Wk = Ws4 + (mt * 64 + 32) * 32 + lane;
#pragma unroll
                for (int k = 0; k < 16; k++) {
                    uint4 a = Wk[k * 32];
                    mma16816(a0c[0], a0c[1], a0c[2], a0c[3], a.x, a.y, a.z, a.w, ba[k].x, ba[k].y);
                    mma16816(a1c[0], a1c[1], a1c[2], a1c[3], a.x, a.y, a.z, a.w, ba[k].z, ba[k].w);
                }
            }
            // chunk 3
            {
                const uint4* Wk = Ws4 + (mt * 64 + 48) * 32 + lane;
#pragma unroll
                for (int k = 0; k < 16; k++) {
                    uint4 a = Wk[k * 32];
                    mma16816(a0c[0], a0c[1], a0c[2], a0c[3], a.x, a.y, a.z, a.w, bbu[k].x, bbu[k].y);
                    mma16816(a1c[0], a1c[1], a1c[2], a1c[3], a.x, a.y, a.z, a.w, bbu[k].z, bbu[k].w);
                }
            }

            {
                int row = mt * 16 + gid;
                int col = nh * 16 + tig * 2;
                *(float2*)&Dsm[row * 66 + col]           = make_float2(a0c[0], a0c[1]);
                *(float2*)&Dsm[(row + 8) * 66 + col]     = make_float2(a0c[2], a0c[3]);
                *(float2*)&Dsm[row * 66 + col + 8]       = make_float2(a1c[0], a1c[1]);
                *(float2*)&Dsm[(row + 8) * 66 + col + 8] = make_float2(a1c[2], a1c[3]);
            }
            __syncthreads();
        }

        // ---------------- epilogue ----------------
        {
            float pre[4][2];
            pre[0][0] = gu.x; pre[1][0] = gu.y; pre[2][0] = gu.z; pre[3][0] = gu.w;
            pre[0][1] = gv.x; pre[1][1] = gv.y; pre[2][1] = gv.z; pre[3][1] = gv.w;
            if (t > 0) {
#pragma unroll
                for (int g = 0; g < 4; g++) {
                    float2 d = *(const float2*)&Dsm[(jl * 4 + g) * 66 + bb];
                    pre[g][0] += d.x; pre[g][1] += d.y;
                }
            }
            unsigned short* hdst = (unsigned short*)g_hfrag[t & 1];
            {
                float f = sigf(pre[0][0]), ig = sigf(pre[1][0]);
                float a = tanhfa(pre[2][0]), o = sigf(pre[3][0]);
                cs0 = f * cs0 + ig * a;
                float h = o * tanhfa(cs0);
                Q[((long)bb * T_ + t) * HD_ + jg] = h;
                hdst[hidx] = __half_as_ushort(__float2half_rn(h));
                if (t == T_ - 1) { hT[(long)bb * HD_ + jg] = h; cT[(long)bb * HD_ + jg] = cs0; }
            }
            {
                float f = sigf(pre[0][1]), ig = sigf(pre[1][1]);
                float a = tanhfa(pre[2][1]), o = sigf(pre[3][1]);
                cs1 = f * cs1 + ig * a;
                float h = o * tanhfa(cs1);
                Q[((long)(bb + 1) * T_ + t) * HD_ + jg] = h;
                hdst[hidx + 32] = __half_as_ushort(__float2half_rn(h));
                if (t == T_ - 1) { hT[(long)(bb + 1) * HD_ + jg] = h; cT[(long)(bb + 1) * HD_ + jg] = cs1; }
            }
        }
        grid_barrier();
    }
}

// ---------------------------------------------------------------------------
extern "C" void kernel_launch(void* const* d_in, const int* in_sizes, int n_in,
                              void* d_out, int out_size) {
    (void)in_sizes; (void)n_in; (void)out_size;
    const float* x  = (const float*)d_in[0];
    const float* Wi = (const float*)d_in[1];
    const float* bi = (const float*)d_in[2];
    const float* Wh = (const float*)d_in[3];
    const float* bh = (const float*)d_in[4];
    float* out = (float*)d_out;

    cudaFuncSetAttribute(lstm_mma_kernel,
                         cudaFuncAttributeMaxDynamicSharedMemorySize, SMEM2);
    cudaFuncSetAttribute(gemm_x_mma,
                         cudaFuncAttributeMaxDynamicSharedMemorySize, SMEMG);

    pack_w_kernel<<<dim3(NBLK, 64), 64>>>(Wh);
    pack_x_kernel<<<dim3(1024, 4), 256>>>(x);
    pack_wi_kernel<<<dim3(512, 4), 256>>>(Wi);
    pack_bias_kernel<<<16, 256>>>(bi, bh);
    gemm_x_mma<<<dim3(128, 32), 256, SMEMG>>>();
    lstm_mma_kernel<<<NBLK, THREADS2, SMEM2>>>(out);
}

// round 17
// speedup vs baseline: 10.1257x; 1.0957x over previous
#include <cuda_runtime.h>
#include <cuda_fp16.h>
#include <math.h>
#include <stdint.h>

#define B_   64
#define T_   256
#define ID_  512
#define HD_  1024
#define G4_  4096

#define NBLK     128
#define THREADS2 512

// phase-2 SMEM: W fragments (64 KB) + 2 D staging buffers
#define OFF_W    0
#define OFF_DSM  65536
#define DSM_STRIDE (32*66)
#define SMEM2    (OFF_DSM + 2*DSM_STRIDE*4)   // 82432
// phase-1 GEMM smem: 2 stages x (A 16KB + B 16KB)
#define SMEMG    65536

// g_gx layout: [t][b][m4], m4 = 4*j + g   (256 MB)
__device__ float g_gx[(size_t)T_ * B_ * G4_];
__device__ uint4 g_wpack[(size_t)NBLK * 4096];       // phase-2 A-fragment images (8 MB)
__device__ uint4 g_hfrag[2][8192];                   // phase-2 B-fragment images
__device__ uint4 g_xfrag[(size_t)1024 * 32 * 32];    // phase-1 A fragments (16 MB)
__device__ uint2 g_wifrag[(size_t)512 * 32 * 32];    // phase-1 B fragments (4 MB)
__device__ float g_biaspk[G4_];                      // bias in m4 order
__device__ unsigned int g_bar_count = 0;
__device__ unsigned int g_bar_gen   = 0;

// ---------------- helpers ----------------------------------------------------
__device__ __forceinline__ uint32_t smem_u32(const void* p) {
    uint32_t a;
    asm("{ .reg .u64 t; cvta.to.shared.u64 t, %1; cvt.u32.u64 %0, t; }" : "=r"(a) : "l"(p));
    return a;
}
__device__ __forceinline__ void cp_async16(uint32_t dst, const void* src) {
    asm volatile("cp.async.cg.shared.global [%0], [%1], 16;" :: "r"(dst), "l"(src) : "memory");
}
__device__ __forceinline__ void cp_commit() { asm volatile("cp.async.commit_group;" ::: "memory"); }
__device__ __forceinline__ void cp_wait1()  { asm volatile("cp.async.wait_group 1;" ::: "memory"); }
__device__ __forceinline__ void cp_wait0()  { asm volatile("cp.async.wait_group 0;" ::: "memory"); }

__device__ __forceinline__ void mma16816(float& d0, float& d1, float& d2, float& d3,
                                         uint32_t a0, uint32_t a1, uint32_t a2, uint32_t a3,
                                         uint32_t b0, uint32_t b1) {
    asm volatile(
        "mma.sync.aligned.m16n8k16.row.col.f32.f16.f16.f32 "
        "{%0,%1,%2,%3}, {%4,%5,%6,%7}, {%8,%9}, {%0,%1,%2,%3};"
        : "+f"(d0), "+f"(d1), "+f"(d2), "+f"(d3)
        : "r"(a0), "r"(a1), "r"(a2), "r"(a3), "r"(b0), "r"(b1));
}
__device__ __forceinline__ uint32_t f2h2(float lo, float hi) {
    __half2 h = __floats2half2_rn(lo, hi);
    return *(uint32_t*)&h;
}
__device__ __forceinline__ uint4 ldcg4(const uint4* p) {
    uint4 v;
    asm volatile("ld.global.cg.v4.u32 {%0,%1,%2,%3}, [%4];"
                 : "=r"(v.x), "=r"(v.y), "=r"(v.z), "=r"(v.w) : "l"(p));
    return v;
}
__device__ __forceinline__ float sigf(float x)   { return __fdividef(1.0f, 1.0f + __expf(-x)); }
__device__ __forceinline__ float tanhfa(float x) { return fmaf(2.0f, sigf(2.0f * x), -1.0f); }

// grid barrier: arrive by atomic, poll by acquire loads
__device__ __forceinline__ void grid_barrier() {
    __syncthreads();
    if (threadIdx.x == 0) {
        unsigned gen;
        asm volatile("ld.acquire.gpu.global.b32 %0, [%1];" : "=r"(gen) : "l"(&g_bar_gen));
        __threadfence();
        unsigned arrived = atomicAdd(&g_bar_count, 1u);
        if (arrived == NBLK - 1) {
            atomicExch(&g_bar_count, 0u);
            __threadfence();
            atomicAdd(&g_bar_gen, 1u);
        } else {
            unsigned g2;
            do {
                asm volatile("ld.acquire.gpu.global.b32 %0, [%1];" : "=r"(g2) : "l"(&g_bar_gen));
            } while (g2 == gen);
        }
        __threadfence();
    }
    __syncthreads();
}

// ---------------------------------------------------------------------------
// Pack Wh into per-block phase-2 A-fragment images (verified layout).
// ---------------------------------------------------------------------------
__global__ void pack_w_kernel(const float* __restrict__ Wh) {
    int bid = blockIdx.x, ks = blockIdx.y;
    int tid = threadIdx.x;          // 64 threads
    int mt = tid >> 5, lane = tid & 31;
    int gid = lane >> 2, tig = lane & 3;

    int r0 = mt * 16 + gid;
    int r1 = r0 + 8;
    int c0 = ((r0 & 3) << 10) + bid * 8 + (r0 >> 2);
    int c1 = ((r1 & 3) << 10) + bid * 8 + (r1 >> 2);
    int k0 = ks * 16 + tig * 2;

    const float* W0 = Wh + c0;
    const float* W1 = Wh + c1;
    uint4 v;
    v.x = f2h2(W0[(size_t)k0 * G4_],       W0[(size_t)(k0 + 1) * G4_]);
    v.y = f2h2(W1[(size_t)k0 * G4_],       W1[(size_t)(k0 + 1) * G4_]);
    v.z = f2h2(W0[(size_t)(k0 + 8) * G4_], W0[(size_t)(k0 + 9) * G4_]);
    v.w = f2h2(W1[(size_t)(k0 + 8) * G4_], W1[(size_t)(k0 + 9) * G4_]);
    g_wpack[(size_t)bid * 4096 + ((mt * 64 + ks) * 32 + lane)] = v;
}

// ---------------------------------------------------------------------------
// Pack x into phase-1 A fragments.
// ---------------------------------------------------------------------------
__global__ void pack_x_kernel(const float* __restrict__ x) {
    int mt = blockIdx.x;
    int w  = threadIdx.x >> 5;
    int ks = blockIdx.y * 8 + w;
    int lane = threadIdx.x & 31;
    int gid = lane >> 2, tig = lane & 3;

    int r0 = mt * 16 + gid;
    int k0 = ks * 16 + tig * 2;
    const float* X0 = x + (size_t)r0 * ID_;
    const float* X1 = X0 + 8 * ID_;
    uint4 v;
    v.x = f2h2(X0[k0],     X0[k0 + 1]);
    v.y = f2h2(X1[k0],     X1[k0 + 1]);
    v.z = f2h2(X0[k0 + 8], X0[k0 + 9]);
    v.w = f2h2(X1[k0 + 8], X1[k0 + 9]);
    g_xfrag[((size_t)mt * 32 + ks) * 32 + lane] = v;
}

// ---------------------------------------------------------------------------
// Pack Wi into phase-1 B fragments: packed col P -> n = (P&3)*1024 + (P>>2).
// ---------------------------------------------------------------------------
__global__ void pack_wi_kernel(const float* __restrict__ Wi) {
    int nt = blockIdx.x;
    int w  = threadIdx.x >> 5;
    int ks = blockIdx.y * 8 + w;
    int lane = threadIdx.x & 31;
    int gid = lane >> 2, tig = lane & 3;

    int P = nt * 8 + gid;
    int n = ((P & 3) << 10) + (P >> 2);
    int k0 = ks * 16 + tig * 2;
    const float* W = Wi + n;
    uint2 v;
    v.x = f2h2(W[(size_t)k0 * G4_],       W[(size_t)(k0 + 1) * G4_]);
    v.y = f2h2(W[(size_t)(k0 + 8) * G4_], W[(size_t)(k0 + 9) * G4_]);
    g_wifrag[((size_t)nt * 32 + ks) * 32 + lane] = v;
}

__global__ void pack_bias_kernel(const float* __restrict__ bi,
                                 const float* __restrict__ bh) {
    int m4 = blockIdx.x * 256 + threadIdx.x;
    int n = ((m4 & 3) << 10) + (m4 >> 2);
    g_biaspk[m4] = bi[n] + bh[n];
}

// ---------------------------------------------------------------------------
// Phase 1: tensor-core GEMM -> g_gx[t][b][m4]
// ---------------------------------------------------------------------------
extern __shared__ __align__(16) char gsm[];

__global__ void __launch_bounds__(256)
gemm_x_mma(void) {
    const int tid  = threadIdx.x;
    const int wid  = tid >> 5;
    const int lane = tid & 31;
    const int gid  = lane >> 2;
    const int tig  = lane & 3;
    const int mblk = blockIdx.x;
    const int jb   = blockIdx.y;
    const int mrow = wid & 1;
    const int ncol = wid >> 1;

    float acc[4][4][4];
#pragma unroll
    for (int mi = 0; mi < 4; mi++)
#pragma unroll
        for (int ni = 0; ni < 4; ni++)
#pragma unroll
            for (int q = 0; q < 4; q++) acc[mi][ni][q] = 0.0f;

    const uint32_t sa = smem_u32(gsm);
    const char* asrc = (const char*)(g_xfrag + (size_t)mblk * 8 * 32 * 32);
    const char* bsrc = (const char*)(g_wifrag + (size_t)jb * 16 * 32 * 32);

    auto copy_stage = [&](int kc, int buf) {
        uint32_t base = sa + buf * 32768;
        int ks0 = kc * 4;
#pragma unroll
        for (int q = 0; q < 4; q++) {
            int idx = q * 256 + tid;
            int mtl = idx >> 7, off = idx & 127;
            cp_async16(base + mtl * 2048 + off * 16,
                       asrc + ((size_t)(mtl * 32 + ks0) * 32) * 16 + off * 16);
        }
#pragma unroll
        for (int q = 0; q < 4; q++) {
            int idx = q * 256 + tid;
            int ntl = idx >> 6, off = idx & 63;
            cp_async16(base + 16384 + ntl * 1024 + off * 16,
                       bsrc + ((size_t)(ntl * 32 + ks0) * 32) * 8 + off * 16);
        }
        cp_commit();
    };

    copy_stage(0, 0);
#pragma unroll 1
    for (int kc = 0; kc < 8; kc++) {
        if (kc < 7) { copy_stage(kc + 1, (kc + 1) & 1); cp_wait1(); }
        else        { cp_wait0(); }
        __syncthreads();

        const uint4* Asm = (const uint4*)(gsm + (kc & 1) * 32768);
        const uint2* Bsm = (const uint2*)(gsm + (kc & 1) * 32768 + 16384);
#pragma unroll
        for (int ksl = 0; ksl < 4; ksl++) {
            uint4 a[4];
            uint2 b[4];
#pragma unroll
            for (int mi = 0; mi < 4; mi++)
                a[mi] = Asm[(mrow * 4 + mi) * 128 + ksl * 32 + lane];
#pragma unroll
            for (int ni = 0; ni < 4; ni++)
                b[ni] = Bsm[(ncol * 4 + ni) * 128 + ksl * 32 + lane];
#pragma unroll
            for (int mi = 0; mi < 4; mi++)
#pragma unroll
                for (int ni = 0; ni < 4; ni++)
                    mma16816(acc[mi][ni][0], acc[mi][ni][1], acc[mi][ni][2], acc[mi][ni][3],
                             a[mi].x, a[mi].y, a[mi].z, a[mi].w, b[ni].x, b[ni].y);
        }
        __syncthreads();
    }

    float2 bias[4];
#pragma unroll
    for (int ni = 0; ni < 4; ni++)
        bias[ni] = *(const float2*)(g_biaspk + jb * 128 + ncol * 32 + ni * 8 + 2 * tig);

#pragma unroll
    for (int mi = 0; mi < 4; mi++) {
        int r0 = mblk * 128 + mrow * 64 + mi * 16 + gid;
        int t0 = r0 & (T_ - 1), b0r = r0 >> 8;
        size_t base0 = (size_t)t0 * (B_ * G4_) + (size_t)b0r * G4_ + jb * 128;
        size_t base1 = base0 + 8 * (size_t)(B_ * G4_);
#pragma unroll
        for (int ni = 0; ni < 4; ni++) {
            int p = ncol * 32 + ni * 8 + 2 * tig;
            *(float2*)(g_gx + base0 + p) =
                make_float2(acc[mi][ni][0] + bias[ni].x, acc[mi][ni][1] + bias[ni].y);
            *(float2*)(g_gx + base1 + p) =
                make_float2(acc[mi][ni][2] + bias[ni].x, acc[mi][ni][3] + bias[ni].y);
        }
    }
}

// ---------------------------------------------------------------------------
// Phase 2: persistent mma.sync recurrence, 512 threads, K split across two
// warpgroups (wg0: K 0..511, wg1: K 512..1023), partial D summed in epilogue.
// ---------------------------------------------------------------------------
extern __shared__ __align__(16) char smem2c[];

__global__ void __launch_bounds__(THREADS2, 1)
lstm_mma_kernel(float* __restrict__ out) {
    const int tid  = threadIdx.x;
    const int wid  = tid >> 5;
    const int lane = tid & 31;
    const int bid  = blockIdx.x;
    const int wg   = wid >> 3;          // warpgroup: K-half
    const int wl   = wid & 7;
    const int mt   = wl & 1;
    const int nh   = wl >> 1;           // 16-batch slice
    const int gid  = lane >> 2;
    const int tig  = lane & 3;

    uint4* Ws4  = (uint4*)(smem2c + OFF_W);
    float* Dsm0 = (float*)(smem2c + OFF_DSM);
    float* Dsm1 = Dsm0 + DSM_STRIDE;
    float* DsmW = wg ? Dsm1 : Dsm0;

    float* Q  = out;
    float* hT = out + (size_t)B_ * T_ * HD_;
    float* cT = hT + (size_t)B_ * HD_;

    {
        const uint4* wsrc = g_wpack + (size_t)bid * 4096;
        for (int i = tid; i < 4096; i += THREADS2) Ws4[i] = wsrc[i];
    }

    // epilogue mapping: thread -> (jl, single batch b)
    const int jl = tid >> 6;            // 0..7
    const int b  = tid & 63;
    const int jg = bid * 8 + jl;
    const int ks_  = jg >> 4;
    const int r_   = jg & 15;
    const int slot = (r_ >> 3) & 1;
    const int tg_  = (r_ & 7) >> 1;
    const int hw_  = r_ & 1;
    const int be   = b & 62;
    const int nh_  = be >> 4;
    const int nt_  = (be >> 3) & 1;
    const int gd_  = be & 7;
    const int hidx = (((((ks_ * 4 + nh_) * 32 + gd_ * 4 + tg_) * 4) + nt_ * 2 + slot) * 2 + hw_)
                     + (b & 1) * 32;

    const int kbase = wg * 32;          // ksl offset for this warpgroup

    float cs = 0.0f;
    __syncthreads();

    for (int t = 0; t < T_; t++) {
        // prefetch this step's gx (one float4: 4 gates for (b, jg))
        const float* gxp = g_gx + (size_t)t * (B_ * G4_) + (size_t)b * G4_ + jg * 4;
        float4 gu = *(const float4*)gxp;

        if (t > 0) {
            float a0c[4] = {0.f, 0.f, 0.f, 0.f};
            float a1c[4] = {0.f, 0.f, 0.f, 0.f};
            const uint4* hbase = g_hfrag[(t - 1) & 1] + nh * 32 + lane + (size_t)kbase * 128;

            uint4 bufA[8], bufB[8];
#pragma unroll
            for (int k = 0; k < 8; k++) bufA[k] = ldcg4(hbase + k * 128);

#pragma unroll
            for (int s = 0; s < 4; s++) {
                // prefetch next sub-chunk
                if (s < 3) {
                    const uint4* p = hbase + (s + 1) * 8 * 128;
                    if (s & 1) {
#pragma unroll
                        for (int k = 0; k < 8; k++) bufA[k] = ldcg4(p + k * 128);
                    } else {
#pragma unroll
                        for (int k = 0; k < 8; k++) bufB[k] = ldcg4(p + k * 128);
                    }
                }
                const uint4* cur = (s & 1) ? bufB : bufA;
                const uint4* Wk = Ws4 + (mt * 64 + kbase + s * 8) * 32 + lane;
#pragma unroll
                for (int k = 0; k < 8; k++) {
                    uint4 a = Wk[k * 32];
                    uint4 bv = cur[k];
                    mma16816(a0c[0], a0c[1], a0c[2], a0c[3], a.x, a.y, a.z, a.w, bv.x, bv.y);
                    mma16816(a1c[0], a1c[1], a1c[2], a1c[3], a.x, a.y, a.z, a.w, bv.z, bv.w);
                }
            }

            {
                int row = mt * 16 + gid;
                int col = nh * 16 + tig * 2;
                *(float2*)&DsmW[row * 66 + col]           = make_float2(a0c[0], a0c[1]);
                *(float2*)&DsmW[(row + 8) * 66 + col]     = make_float2(a0c[2], a0c[3]);
                *(float2*)&DsmW[row * 66 + col + 8]       = make_float2(a1c[0], a1c[1]);
                *(float2*)&DsmW[(row + 8) * 66 + col + 8] = make_float2(a1c[2], a1c[3]);
            }
            __syncthreads();
        }

        // ---------------- epilogue: 1 (j, b) per thread ----------------
        {
            float pre0 = gu.x, pre1 = gu.y, pre2 = gu.z, pre3 = gu.w;
            if (t > 0) {
                int rb = (jl * 4) * 66 + b;
                pre0 += Dsm0[rb]           + Dsm1[rb];
                pre1 += Dsm0[rb + 66]      + Dsm1[rb + 66];
                pre2 += Dsm0[rb + 132]     + Dsm1[rb + 132];
                pre3 += Dsm0[rb + 198]     + Dsm1[rb + 198];
            }
            float f = sigf(pre0), ig = sigf(pre1);
            float a = tanhfa(pre2), o = sigf(pre3);
            cs = f * cs + ig * a;
            float h = o * tanhfa(cs);
            Q[((long)b * T_ + t) * HD_ + jg] = h;
            ((unsigned short*)g_hfrag[t & 1])[hidx] = __half_as_ushort(__float2half_rn(h));
            if (t == T_ - 1) {
                hT[(long)b * HD_ + jg] = h;
                cT[(long)b * HD_ + jg] = cs;
            }
        }
        grid_barrier();
    }
}

// ---------------------------------------------------------------------------
extern "C" void kernel_launch(void* const* d_in, const int* in_sizes, int n_in,
                              void* d_out, int out_size) {
    (void)in_sizes; (void)n_in; (void)out_size;
    const float* x  = (const float*)d_in[0];
    const float* Wi = (const float*)d_in[1];
    const float* bi = (const float*)d_in[2];
    const float* Wh = (const float*)d_in[3];
    const float* bh = (const float*)d_in[4];
    float* out = (float*)d_out;

    cudaFuncSetAttribute(lstm_mma_kernel,
                         cudaFuncAttributeMaxDynamicSharedMemorySize, SMEM2);
    cudaFuncSetAttribute(gemm_x_mma,
                         cudaFuncAttributeMaxDynamicSharedMemorySize, SMEMG);

    pack_w_kernel<<<dim3(NBLK, 64), 64>>>(Wh);
    pack_x_kernel<<<dim3(1024, 4), 256>>>(x);
    pack_wi_kernel<<<dim3(512, 4), 256>>>(Wi);
    pack_bias_kernel<<<16, 256>>>(bi, bh);
    gemm_x_mma<<<dim3(128, 32), 256, SMEMG>>>();
    lstm_mma_kernel<<<NBLK, THREADS2, SMEM2>>>(out);
}